// round 11
// baseline (speedup 1.0000x reference)
#include <cuda_runtime.h>
#include <cuda_bf16.h>
#include <math.h>

// ---------------- constants ----------------
#define TPIF 6.283185307179586f
// output section offsets (floats)
#define OFF_Y    0
#define OFF_LAT  276480
#define OFF_SIG  291968
#define OFF_P    307456
#define OFF_FQ   307584
#define OFF_A    307712
#define OFF_B    307840
#define OFF_YP   307968

// ---------------- scratch ----------------
__device__ float  g_P[(size_t)16*24*121*240];   // S then k-prefix: [b][o][k][Q]
__device__ float  g_w2t[24*121*8 + 32];         // enc_w2 transposed [o][k][e] (+pad for prefetch)
__device__ float4 g_twid4[121*64];              // (cs,cs,sn,sn) [t][f]
__device__ float  g_ys[(size_t)16*8*240*121];   // ysin [b][e][n][t]
__device__ float  g_scy[16*8*360];              // padded yc
__device__ float  g_dpre[16*24*240];            // dec conv1 pre-BN
__device__ float  g_bnm[24];
__device__ float  g_bni[24];
__device__ float  g_ddp[16*24*360];             // tanh(BN(d)) padded

#define FULLMASK 0xffffffffu
__device__ __forceinline__ float wred(float v) {
    v += __shfl_xor_sync(FULLMASK, v, 16);
    v += __shfl_xor_sync(FULLMASK, v, 8);
    v += __shfl_xor_sync(FULLMASK, v, 4);
    v += __shfl_xor_sync(FULLMASK, v, 2);
    v += __shfl_xor_sync(FULLMASK, v, 1);
    return v;
}

// packed f32x2 helpers
__device__ __forceinline__ unsigned long long dup2(float x) {
    unsigned long long r; unsigned u = __float_as_uint(x);
    asm("mov.b64 %0, {%1, %1};" : "=l"(r) : "r"(u));
    return r;
}
__device__ __forceinline__ void ffma2(unsigned long long& d, unsigned long long a, unsigned long long b) {
    asm("fma.rn.f32x2 %0, %1, %2, %0;" : "+l"(d) : "l"(a), "l"(b));
}
__device__ __forceinline__ float2 unpack2(unsigned long long v) {
    unsigned lo, hi;
    asm("mov.b64 {%0, %1}, %2;" : "=r"(lo), "=r"(hi) : "l"(v));
    return make_float2(__uint_as_float(lo), __uint_as_float(hi));
}

// ---------------- prep: twiddles + w2 transpose ----------------
__global__ void prep_k(const float* __restrict__ w2) {
    int i = blockIdx.x * blockDim.x + threadIdx.x;
    int stride = gridDim.x * blockDim.x;
    for (int idx = i; idx < 121 * 61; idx += stride) {
        int t = idx / 61, f = idx - 61 * t;
        float fr = (float)fmod((double)(2 * f * t) / 121.0, 2.0);
        float sn, cs; sincospif(fr, &sn, &cs);
        g_twid4[t * 64 + f] = make_float4(cs, cs, sn, sn);
    }
    for (int idx = i; idx < 24 * 121 * 8; idx += stride) {
        int e = idx & 7, ok = idx >> 3;
        int o = ok / 121, k = ok - 121 * o;
        g_w2t[idx] = w2[(e * 24 + o) * 121 + k];
    }
}

// ---------------- S[b,o,k,Q] ----------------
__global__ void __launch_bounds__(256) s_kernel(const float* __restrict__ x,
                                                const float* __restrict__ w1) {
    extern __shared__ float sm[];
    float* xs = sm;               // 72 x 244 (dup-padded)
    float* ws = sm + 72 * 244;    // 24 x 72
    const int k = blockIdx.x, b = blockIdx.y;
    const int tid = threadIdx.x;

    for (int idx = tid; idx < 72 * 240; idx += 256) {
        int i = idx / 240, c = idx - 240 * i;
        xs[i * 244 + c] = x[(b * 72 + i) * 240 + c];
    }
    for (int idx = tid; idx < 72 * 4; idx += 256) {
        int i = idx >> 2, j = idx & 3;
        xs[i * 244 + 240 + j] = x[(b * 72 + i) * 240 + j];
    }
    for (int idx = tid; idx < 24 * 72; idx += 256)
        ws[idx] = w1[idx * 121 + k];
    __syncthreads();

    for (int task = tid; task < 360; task += 256) {
        int og = task / 60, qg = task - 60 * og;
        int o0 = og * 4, Q0 = qg * 4;
        float acc[4][4];
        #pragma unroll
        for (int a = 0; a < 4; a++)
            #pragma unroll
            for (int q = 0; q < 4; q++) acc[a][q] = 0.f;
        int base = Q0 + k + 120; if (base >= 240) base -= 240;
        const float* xb = xs + base;
        const float* wp0 = ws + (o0 + 0) * 72;
        const float* wp1 = ws + (o0 + 1) * 72;
        const float* wp2 = ws + (o0 + 2) * 72;
        const float* wp3 = ws + (o0 + 3) * 72;
        #pragma unroll 4
        for (int i = 0; i < 72; i++) {
            const float* xr = xb + i * 244;
            float x0 = xr[0], x1 = xr[1], x2 = xr[2], x3 = xr[3];
            float w0 = wp0[i], w1v = wp1[i], w2v = wp2[i], w3v = wp3[i];
            acc[0][0]=fmaf(w0,x0,acc[0][0]); acc[0][1]=fmaf(w0,x1,acc[0][1]);
            acc[0][2]=fmaf(w0,x2,acc[0][2]); acc[0][3]=fmaf(w0,x3,acc[0][3]);
            acc[1][0]=fmaf(w1v,x0,acc[1][0]); acc[1][1]=fmaf(w1v,x1,acc[1][1]);
            acc[1][2]=fmaf(w1v,x2,acc[1][2]); acc[1][3]=fmaf(w1v,x3,acc[1][3]);
            acc[2][0]=fmaf(w2v,x0,acc[2][0]); acc[2][1]=fmaf(w2v,x1,acc[2][1]);
            acc[2][2]=fmaf(w2v,x2,acc[2][2]); acc[2][3]=fmaf(w2v,x3,acc[2][3]);
            acc[3][0]=fmaf(w3v,x0,acc[3][0]); acc[3][1]=fmaf(w3v,x1,acc[3][1]);
            acc[3][2]=fmaf(w3v,x2,acc[3][2]); acc[3][3]=fmaf(w3v,x3,acc[3][3]);
        }
        size_t pbase = ((size_t)(b * 24 + o0) * 121 + k) * 240 + Q0;
        #pragma unroll
        for (int oo = 0; oo < 4; oo++)
            #pragma unroll
            for (int qq = 0; qq < 4; qq++)
                g_P[pbase + (size_t)oo * 121 * 240 + qq] = acc[oo][qq];
    }
}

// ---------------- prefix over k ----------------
__global__ void prefix_k() {
    int bo = blockIdx.x, Q = threadIdx.x;
    if (Q < 240) {
        size_t base = (size_t)bo * 121 * 240 + Q;
        float acc = 0.f;
        for (int k = 0; k < 121; k++) {
            acc += g_P[base + (size_t)k * 240];
            g_P[base + (size_t)k * 240] = acc;
        }
    }
}

// 8 packed FMAs for one k (weights pair w, h values h0..h3 for t offsets 0..3)
#define K8(w, h0, h1, h2, h3) \
    ffma2(a00, w.x, h0); ffma2(a01, w.x, h1); ffma2(a02, w.x, h2); ffma2(a03, w.x, h3); \
    ffma2(a10, w.y, h0); ffma2(a11, w.y, h1); ffma2(a12, w.y, h2); ffma2(a13, w.y, h3);

// ---------------- encoder v3 ----------------
// block = 128 thr = 4 warps = 2 windows (2 warps each, split by e-half).
// smem per window: hp 24x252 + lt 122x8 (transposed) = 7024 floats.
__global__ void __launch_bounds__(128, 4) encode_k(
    const float* __restrict__ lna, const float* __restrict__ lnb,
    const float* __restrict__ b2, const float* __restrict__ fcw,
    const float* __restrict__ fcb, float* __restrict__ out)
{
    extern __shared__ float sm[];
    const int warp = threadIdx.x >> 5, lane = threadIdx.x & 31;
    const int wwin = warp >> 1, whalf = warp & 1;
    float* hpw = sm + wwin * 7024;
    float* lt  = hpw + 6048;       // lt[t*8 + e]
    const int s = blockIdx.x * 2 + wwin;
    const int b = s / 240, n = s - b * 240;

    for (int i = threadIdx.x; i < 2 * 6048; i += 128) {
        int w2i = i / 6048, r = i - w2i * 6048;
        sm[w2i * 7024 + r] = 0.f;
    }
    __syncthreads();

    // ---- conv1 via prefix diffs + LayerNorm + tanh (12 o's per warp) ----
    const size_t pb0 = (size_t)(b * 24) * 121 * 240;
    for (int oo = 0; oo < 12; oo++) {
        int o = whalf * 12 + oo;
        const float* P = g_P + pb0 + (size_t)o * 121 * 240;
        float hv[4]; float s1 = 0.f, s2 = 0.f;
        #pragma unroll
        for (int j = 0; j < 4; j++) {
            int t = lane + 32 * j;
            float h = 0.f;
            if (t < 121) {
                int Q = n + t; if (Q >= 240) Q -= 240;
                if (t < 60) h = P[120 * 240 + Q] - P[(59 - t) * 240 + Q];
                else        h = P[(180 - t) * 240 + Q];
                s1 += h; s2 += h * h;
            }
            hv[j] = h;
        }
        s1 = wred(s1); s2 = wred(s2);
        float mean = s1 * (1.f / 121.f);
        float var = (s2 - s1 * mean) * (1.f / 120.f);
        float inv = 1.f / (sqrtf(var) + 1e-5f);
        #pragma unroll
        for (int j = 0; j < 4; j++) {
            int t = lane + 32 * j;
            if (t < 121)
                hpw[o * 252 + 60 + t] = tanhf((hv[j] - mean) * inv * lna[t] + lnb[t]);
        }
    }
    __syncthreads();

    // ---- conv2: 4 e's x 4 t's per lane, f32x2, group-of-4 + weight prefetch ----
    const int ebase = whalf * 4;
    const int t0 = 4 * lane;
    unsigned long long a00=0,a01=0,a02=0,a03=0,a10=0,a11=0,a12=0,a13=0;

    for (int o = 0; o < 24; o++) {
        const float* hrow = hpw + o * 252 + t0;
        const ulonglong2* wp = (const ulonglong2*)(g_w2t + o * 968 + ebase);
        float4 cur = *(const float4*)hrow;
        unsigned long long d0 = dup2(cur.x), d1 = dup2(cur.y),
                           d2 = dup2(cur.z), d3 = dup2(cur.w);
        ulonglong2 wA = wp[0], wB = wp[2], wC = wp[4], wD = wp[6];
        #pragma unroll 2
        for (int g = 0; g < 30; g++) {
            float4 nxt = *(const float4*)(hrow + 4 * g + 4);
            // prefetch next group's weights (pad makes tail reads safe)
            ulonglong2 nA = wp[8 * g + 8],  nB = wp[8 * g + 10],
                       nC = wp[8 * g + 12], nD = wp[8 * g + 14];
            unsigned long long e0 = dup2(nxt.x), e1 = dup2(nxt.y),
                               e2 = dup2(nxt.z), e3 = dup2(nxt.w);
            K8(wA, d0, d1, d2, d3)
            K8(wB, d1, d2, d3, e0)
            K8(wC, d2, d3, e0, e1)
            K8(wD, d3, e0, e1, e2)
            d0 = e0; d1 = e1; d2 = e2; d3 = e3;
            wA = nA; wB = nB; wC = nC; wD = nD;
        }
        // k = 120 (wA holds wp[240] from last prefetch)
        K8(wA, d0, d1, d2, d3)
    }

    // store latent transposed: lt[t*8 + e], float2 per e-pair
    {
        float be0 = b2[ebase], be1 = b2[ebase + 1];
        float be2 = b2[ebase + 2], be3 = b2[ebase + 3];
        unsigned long long ac0[4] = {a00, a01, a02, a03};
        unsigned long long ac1[4] = {a10, a11, a12, a13};
        #pragma unroll
        for (int j = 0; j < 4; j++) {
            int t = t0 + j;
            if (t < 121) {
                float2 v = unpack2(ac0[j]);
                float2 u = unpack2(ac1[j]);
                *(float2*)&lt[t * 8 + ebase]     = make_float2(v.x + be0, v.y + be1);
                *(float2*)&lt[t * 8 + ebase + 2] = make_float2(u.x + be2, u.y + be3);
            }
        }
    }
    __syncwarp();

    // ---- DFT (bins 1..60 over lanes, 2 rounds), packed over e-pairs ----
    float num[4] = {0.f,0.f,0.f,0.f}, den[4] = {0.f,0.f,0.f,0.f};
    #pragma unroll
    for (int round = 0; round < 2; round++) {
        int fi = lane + 32 * round;
        if (fi < 60) {
            unsigned long long cr01=0, cr23=0, ci01=0, ci23=0;
            const ulonglong2* tw = (const ulonglong2*)g_twid4 + fi + 1;
            const float* ltb = lt + ebase;
            for (int t = 0; t < 121; t++) {
                ulonglong2 w2v = tw[t * 64];                       // (cs,cs),(sn,sn)
                ulonglong2 l   = *(const ulonglong2*)(ltb + t * 8); // (e0,e1),(e2,e3)
                ffma2(cr01, w2v.x, l.x); ffma2(cr23, w2v.x, l.y);
                ffma2(ci01, w2v.y, l.x); ffma2(ci23, w2v.y, l.y);
            }
            float2 c01 = unpack2(cr01), c23 = unpack2(cr23);
            float2 s01 = unpack2(ci01), s23 = unpack2(ci23);
            float cr[4] = {c01.x, c01.y, c23.x, c23.y};
            float ci[4] = {s01.x, s01.y, s23.x, s23.y};
            float fr = 0.5f * (float)(fi + 1);
            #pragma unroll
            for (int e = 0; e < 4; e++) {
                float pw = cr[e] * cr[e] + ci[e] * ci[e];
                num[e] = fmaf(pw, fr, num[e]);
                den[e] += pw;
            }
        }
    }
    #pragma unroll
    for (int e = 0; e < 4; e++) { num[e] = wred(num[e]); den[e] = wred(den[e]); }

    // ---- fc phase + DC ----
    float sb[4] = {0.f,0.f,0.f,0.f}, sv0[4] = {0.f,0.f,0.f,0.f}, sv1[4] = {0.f,0.f,0.f,0.f};
    #pragma unroll
    for (int j = 0; j < 4; j++) {
        int t = lane + 32 * j;
        if (t < 121) {
            float4 l4 = *(const float4*)(lt + t * 8 + ebase);
            float le[4] = {l4.x, l4.y, l4.z, l4.w};
            #pragma unroll
            for (int e = 0; e < 4; e++) {
                int eg = ebase + e;
                sb[e] += le[e];
                sv0[e] = fmaf(le[e], fcw[(eg * 2 + 0) * 121 + t], sv0[e]);
                sv1[e] = fmaf(le[e], fcw[(eg * 2 + 1) * 121 + t], sv1[e]);
            }
        }
    }
    float bo_[4], v0[4], v1[4];
    #pragma unroll
    for (int e = 0; e < 4; e++) {
        int eg = ebase + e;
        bo_[e] = wred(sb[e]) * (1.f / 121.f);
        v0[e] = wred(sv0[e]) + fcb[eg * 2];
        v1[e] = wred(sv1[e]) + fcb[eg * 2 + 1];
    }

    float fe[4], am[4], ph[4];
    #pragma unroll
    for (int e = 0; e < 4; e++) {
        fe[e] = num[e] / den[e];
        am[e] = 2.f * sqrtf(den[e]) * (1.f / 121.f);
        ph[e] = atan2f(v1[e], v0[e]);
    }

    if (n == 0) {
        if (lane == 0) {
            #pragma unroll
            for (int e = 0; e < 4; e++) {
                int eg = ebase + e;
                out[OFF_P  + b * 8 + eg] = ph[e] * (1.f / TPIF);
                out[OFF_FQ + b * 8 + eg] = fe[e];
                out[OFF_A  + b * 8 + eg] = am[e];
                out[OFF_B  + b * 8 + eg] = bo_[e];
            }
        }
        #pragma unroll
        for (int e = 0; e < 4; e++) {
            int eg = ebase + e;
            for (int t = lane; t < 121; t += 32)
                out[OFF_LAT + (b * 8 + eg) * 121 + t] = lt[t * 8 + eg];
        }
    }

    // ---- sinusoid resynthesis ----
    #pragma unroll
    for (int e = 0; e < 4; e++) {
        int eg = ebase + e;
        float* yd = g_ys + ((size_t)(b * 8 + eg) * 240 + n) * 121;
        float w = TPIF * fe[e];
        for (int t = lane; t < 121; t += 32) {
            float arg = fmaf(w, (float)(t - 60) * (1.f / 60.f), ph[e]);
            yd[t] = fmaf(am[e], sinf(arg), bo_[e]);
        }
    }
}

// ---------------- overlap-add (deterministic gather) ----------------
__global__ void overlap_k(float* __restrict__ out) {
    int be = blockIdx.x;
    int j = threadIdx.x; // 0..359
    const float* ys = g_ys + (size_t)be * 240 * 121;
    int tlo = j - 239; if (tlo < 0) tlo = 0;
    int thi = j < 120 ? j : 120;
    float s = 0.f;
    for (int t = tlo; t <= thi; t++) s += ys[(j - t) * 121 + t];
    float w = (j < 121) ? (float)(j + 1) : (j > 239 ? (float)(360 - j) : 121.f);
    float sig = s / w;
    if (j < 121) out[OFF_SIG + be * 121 + j] = sig;
    g_scy[be * 360 + j] = (j >= 60 && j < 300) ? sig : 0.f;
}

// ---------------- decoder conv1 (bias skipped: cancels in BN) ----------------
__global__ void __launch_bounds__(256) dec1_k(const float* __restrict__ dw1) {
    __shared__ float ys[8 * 360], ws[8 * 121];
    int b = blockIdx.x, o = blockIdx.y, tid = threadIdx.x;
    for (int i = tid; i < 8 * 360; i += 256)
        ys[i] = g_scy[(b * 8 + i / 360) * 360 + i % 360];
    for (int i = tid; i < 8 * 121; i += 256)
        ws[i] = dw1[o * 8 * 121 + i];
    __syncthreads();
    if (tid < 240) {
        float acc = 0.f;
        #pragma unroll
        for (int e = 0; e < 8; e++) {
            const float* yr = ys + e * 360 + tid;
            const float* wr = ws + e * 121;
            #pragma unroll 4
            for (int k = 0; k < 121; k++) acc = fmaf(wr[k], yr[k], acc);
        }
        g_dpre[(b * 24 + o) * 240 + tid] = acc;
    }
}

// ---------------- BN stats (deterministic tree) ----------------
__global__ void bnstat_k() {
    __shared__ float r1[256], r2[256];
    int o = blockIdx.x, tid = threadIdx.x;
    float s1 = 0.f, s2 = 0.f;
    for (int i = tid; i < 3840; i += 256) {
        int bb = i / 240, t = i - 240 * bb;
        float v = g_dpre[(bb * 24 + o) * 240 + t];
        s1 += v; s2 += v * v;
    }
    r1[tid] = s1; r2[tid] = s2; __syncthreads();
    for (int st = 128; st > 0; st >>= 1) {
        if (tid < st) { r1[tid] += r1[tid + st]; r2[tid] += r2[tid + st]; }
        __syncthreads();
    }
    if (tid == 0) {
        float m = r1[0] * (1.f / 3840.f);
        g_bnm[o] = m;
        g_bni[o] = rsqrtf(r2[0] * (1.f / 3840.f) - m * m + 1e-5f);
    }
}

__global__ void bnapply_k(const float* __restrict__ gam, const float* __restrict__ bet) {
    int idx = blockIdx.x * blockDim.x + threadIdx.x;
    if (idx >= 16 * 24 * 360) return;
    int tau = idx % 360, bo = idx / 360;
    int o = bo % 24;
    float v = 0.f;
    if (tau >= 60 && tau < 300)
        v = tanhf((g_dpre[bo * 240 + tau - 60] - g_bnm[o]) * g_bni[o] * gam[o] + bet[o]);
    g_ddp[idx] = v;
}

// ---------------- decoder conv2 + outputs ----------------
__global__ void __launch_bounds__(64) dec2_k(const float* __restrict__ dw2,
                                             const float* __restrict__ db2,
                                             float* __restrict__ out) {
    __shared__ float dd[24 * 360], ws[24 * 121];
    int b = blockIdx.x, c = blockIdx.y, tid = threadIdx.x;
    for (int i = tid; i < 24 * 360; i += 64) dd[i] = g_ddp[b * 24 * 360 + i];
    for (int i = tid; i < 24 * 121; i += 64) ws[i] = dw2[c * 24 * 121 + i];
    __syncthreads();
    if (tid < 60) {
        int t0 = tid * 4;
        float a0 = 0.f, a1 = 0.f, a2 = 0.f, a3 = 0.f;
        for (int o = 0; o < 24; o++) {
            const float* dr = dd + o * 360 + t0;
            const float* wr = ws + o * 121;
            float x0 = dr[0], x1 = dr[1], x2 = dr[2];
            #pragma unroll 4
            for (int k = 0; k < 121; k++) {
                float w = wr[k]; float x3 = dr[k + 3];
                a0 = fmaf(w, x0, a0); a1 = fmaf(w, x1, a1);
                a2 = fmaf(w, x2, a2); a3 = fmaf(w, x3, a3);
                x0 = x1; x1 = x2; x2 = x3;
            }
        }
        float bias = db2[c];
        float r[4] = { a0 + bias, a1 + bias, a2 + bias, a3 + bias };
        size_t yb = (size_t)(b * 72 + c) * 240 + t0;
        #pragma unroll
        for (int q = 0; q < 4; q++) {
            out[OFF_Y + yb + q] = r[q];
            int t = t0 + q;
            if (t < 121) out[OFF_YP + (b * 72 + c) * 121 + t] = r[q];
        }
    }
}

// ---------------- launch ----------------
extern "C" void kernel_launch(void* const* d_in, const int* in_sizes, int n_in,
                              void* d_out, int out_size) {
    const float* x   = (const float*)d_in[0];
    const float* w1  = (const float*)d_in[1];
    const float* lna = (const float*)d_in[3];
    const float* lnb = (const float*)d_in[4];
    const float* w2  = (const float*)d_in[5];
    const float* b2  = (const float*)d_in[6];
    const float* fcw = (const float*)d_in[7];
    const float* fcb = (const float*)d_in[8];
    const float* dw1 = (const float*)d_in[9];
    const float* bng = (const float*)d_in[11];
    const float* bnb = (const float*)d_in[12];
    const float* dw2 = (const float*)d_in[13];
    const float* db2 = (const float*)d_in[14];
    float* out = (float*)d_out;

    const int SMEM_S = (72 * 244 + 24 * 72) * 4;      // 77184
    const int SMEM_E = 2 * 7024 * 4;                  // 56192
    cudaFuncSetAttribute(s_kernel, cudaFuncAttributeMaxDynamicSharedMemorySize, SMEM_S);
    cudaFuncSetAttribute(encode_k, cudaFuncAttributeMaxDynamicSharedMemorySize, SMEM_E);

    prep_k<<<64, 256>>>(w2);
    s_kernel<<<dim3(121, 16), 256, SMEM_S>>>(x, w1);
    prefix_k<<<384, 256>>>();
    encode_k<<<1920, 128, SMEM_E>>>(lna, lnb, b2, fcw, fcb, out);
    overlap_k<<<128, 360>>>(out);
    dec1_k<<<dim3(16, 24), 256>>>(dw1);
    bnstat_k<<<24, 256>>>();
    bnapply_k<<<540, 256>>>(bng, bnb);
    dec2_k<<<dim3(16, 72), 64>>>(dw2, db2, out);
}